// round 11
// baseline (speedup 1.0000x reference)
#include <cuda_runtime.h>
#include <cuda_bf16.h>
#include <cstdint>

// out[v, g, v2, d] = W[GE[v,g] % 3, d] + b[d]
//   GE: [512, 4, 1] int32, W: [3, 64] f32, b: [64] f32
//   out: [512, 4, 512, 64] f32  (256 MB) — constant along v2.
//
// Persistent grid: 1216 resident CTAs (152 SMs x occ 8) grid-stride over
// 8192 work items of 32 KB (128 copy-rows each). No CTA churn, no wave
// tail; every warp stays in its store loop for the whole kernel.

static constexpr int V = 512;
static constexpr int G = 4;
static constexpr int D = 64;
static constexpr int THREADS = 256;
static constexpr int CHUNKS = D / 8;                  // 8 threads per row
static constexpr int ROWS_PER_IT = THREADS / CHUNKS;  // 32 rows per iteration
static constexpr int SPLIT = 4;                       // work items per pair
static constexpr int ROWS_PER_ITEM = V / SPLIT;       // 128 copy rows (32 KB)
static constexpr int N_ITEMS = V * G * SPLIT;         // 8192
static constexpr int GRID = 152 * 8;                  // persistent CTAs

__device__ __forceinline__ void stg256(float* p, const float v[8])
{
    asm volatile(
        "st.global.v8.b32 [%0], {%1,%2,%3,%4,%5,%6,%7,%8};"
        :: "l"(p),
           "r"(__float_as_uint(v[0])), "r"(__float_as_uint(v[1])),
           "r"(__float_as_uint(v[2])), "r"(__float_as_uint(v[3])),
           "r"(__float_as_uint(v[4])), "r"(__float_as_uint(v[5])),
           "r"(__float_as_uint(v[6])), "r"(__float_as_uint(v[7]))
        : "memory");
}

__global__ void __launch_bounds__(THREADS, 8)
gembed_persist_kernel(const int* __restrict__ GE,
                      const float* __restrict__ W,
                      const float* __restrict__ b,
                      float* __restrict__ out)
{
    const int t     = threadIdx.x;
    const int chunk = t & (CHUNKS - 1);           // 8-float chunk of the row
    const int r0    = t >> 3;                     // starting copy row (0..31)

    // Bias is loop-invariant: load once per thread.
    const float4 b0 = reinterpret_cast<const float4*>(b)[chunk * 2 + 0];
    const float4 b1 = reinterpret_cast<const float4*>(b)[chunk * 2 + 1];

    for (int item = blockIdx.x; item < N_ITEMS; item += GRID) {
        const int pair = item >> 2;               // v*G + g
        const int part = item & 3;                // which 128-row slice

        const int idx = GE[pair] % 3;             // GE in [0,3)

        const float4 w0 = reinterpret_cast<const float4*>(W + idx * D)[chunk * 2 + 0];
        const float4 w1 = reinterpret_cast<const float4*>(W + idx * D)[chunk * 2 + 1];

        float val[8];
        val[0] = w0.x + b0.x;  val[1] = w0.y + b0.y;
        val[2] = w0.z + b0.z;  val[3] = w0.w + b0.w;
        val[4] = w1.x + b1.x;  val[5] = w1.y + b1.y;
        val[6] = w1.z + b1.z;  val[7] = w1.w + b1.w;

        float* base = out + (size_t)pair * (size_t)(V * D)
                          + (size_t)part * (size_t)(ROWS_PER_ITEM * D)
                          + (size_t)(chunk * 8);

        #pragma unroll
        for (int r = r0; r < ROWS_PER_ITEM; r += ROWS_PER_IT) {
            stg256(base + r * D, val);
        }
    }
}

extern "C" void kernel_launch(void* const* d_in, const int* in_sizes, int n_in,
                              void* d_out, int out_size)
{
    const int*   GE = (const int*)d_in[0];
    const float* W  = (const float*)d_in[1];
    const float* b  = (const float*)d_in[2];
    float* out = (float*)d_out;

    (void)in_sizes; (void)n_in; (void)out_size;

    gembed_persist_kernel<<<GRID, THREADS>>>(GE, W, b, out);
}

// round 12
// speedup vs baseline: 1.1522x; 1.1522x over previous
#include <cuda_runtime.h>
#include <cuda_bf16.h>
#include <cstdint>

// out[v, g, v2, d] = W[GE[v,g] % 3, d] + b[d]
//   GE: [512, 4, 1] int32, W: [3, 64] f32, b: [64] f32
//   out: [512, 4, 512, 64] f32  (256 MB) — constant along v2.
//
// FINAL (measured optimum of the R2-R10 sweep): pure store-stream kernel.
// 16384 blocks x 16 KB work quanta (SPLIT=8), 256 threads, 2 x STG.256 per
// thread. Concurrency sweep showed drain rate saturates here (~5.42 TB/s,
// ~67% of combined-R/W HBM spec = write-stream floor). Store-width, cache-op
// (.cs/.cg), TMA-bulk, and persistent-grid variants were all neutral or worse.

static constexpr int V = 512;
static constexpr int G = 4;
static constexpr int D = 64;
static constexpr int THREADS = 256;
static constexpr int CHUNKS = D / 8;                  // 8 threads per row
static constexpr int ROWS_PER_IT = THREADS / CHUNKS;  // 32 rows per iteration
static constexpr int SPLIT = 8;                       // blocks per (v,g) pair
static constexpr int ROWS_PER_BLOCK = V / SPLIT;      // 64 copy rows (16 KB)

__device__ __forceinline__ void stg256(float* p, const float v[8])
{
    asm volatile(
        "st.global.v8.b32 [%0], {%1,%2,%3,%4,%5,%6,%7,%8};"
        :: "l"(p),
           "r"(__float_as_uint(v[0])), "r"(__float_as_uint(v[1])),
           "r"(__float_as_uint(v[2])), "r"(__float_as_uint(v[3])),
           "r"(__float_as_uint(v[4])), "r"(__float_as_uint(v[5])),
           "r"(__float_as_uint(v[6])), "r"(__float_as_uint(v[7]))
        : "memory");
}

__global__ void __launch_bounds__(THREADS, 8)
gembed_bcast_kernel(const int* __restrict__ GE,
                    const float* __restrict__ W,
                    const float* __restrict__ b,
                    float* __restrict__ out)
{
    const int blk   = blockIdx.x;                 // 0..16383
    const int pair  = blk >> 3;                   // v*G + g
    const int part  = blk & 7;                    // which 64-row slice
    const int t     = threadIdx.x;
    const int chunk = t & (CHUNKS - 1);           // 8-float chunk of the row
    const int r0    = t >> 3;                     // starting copy row (0..31)

    const int idx = GE[pair] % 3;                 // GE in [0,3)

    const float4 w0 = reinterpret_cast<const float4*>(W + idx * D)[chunk * 2 + 0];
    const float4 w1 = reinterpret_cast<const float4*>(W + idx * D)[chunk * 2 + 1];
    const float4 b0 = reinterpret_cast<const float4*>(b)[chunk * 2 + 0];
    const float4 b1 = reinterpret_cast<const float4*>(b)[chunk * 2 + 1];

    float val[8];
    val[0] = w0.x + b0.x;  val[1] = w0.y + b0.y;
    val[2] = w0.z + b0.z;  val[3] = w0.w + b0.w;
    val[4] = w1.x + b1.x;  val[5] = w1.y + b1.y;
    val[6] = w1.z + b1.z;  val[7] = w1.w + b1.w;

    // This block streams 64 copies (16 KB): 2 x STG.256 per thread, each
    // warp instruction writing 1 KB contiguous.
    float* base = out + (size_t)pair * (size_t)(V * D)
                      + (size_t)part * (size_t)(ROWS_PER_BLOCK * D)
                      + (size_t)(chunk * 8);

    #pragma unroll
    for (int r = r0; r < ROWS_PER_BLOCK; r += ROWS_PER_IT) {
        stg256(base + r * D, val);
    }
}

extern "C" void kernel_launch(void* const* d_in, const int* in_sizes, int n_in,
                              void* d_out, int out_size)
{
    const int*   GE = (const int*)d_in[0];
    const float* W  = (const float*)d_in[1];
    const float* b  = (const float*)d_in[2];
    float* out = (float*)d_out;

    (void)in_sizes; (void)n_in; (void)out_size;

    gembed_bcast_kernel<<<V * G * SPLIT, THREADS>>>(GE, W, b, out);
}